// round 1
// baseline (speedup 1.0000x reference)
#include <cuda_runtime.h>
#include <cuda_bf16.h>
#include <math_constants.h>

// Problem constants
#define NROWS 32768      // 8 * 4096
#define KCODES 8192
#define DIM 256

#define TM 64
#define TN 64
#define DCHUNK 16

// Scratch (no allocations allowed)
__device__ float g_xsq[NROWS];
__device__ float g_csq[KCODES];

// ---------------------------------------------------------------------------
// Row squared-norm kernel: one warp per row of 256 floats.
// which == 0 -> write g_xsq, which == 1 -> write g_csq
// ---------------------------------------------------------------------------
__global__ __launch_bounds__(256) void vq_rownorm(const float* __restrict__ v,
                                                  int nrows, int which) {
    int warp = (blockIdx.x * blockDim.x + threadIdx.x) >> 5;
    int lane = threadIdx.x & 31;
    if (warp >= nrows) return;
    const float4* p = (const float4*)(v + (size_t)warp * DIM);
    float s = 0.f;
#pragma unroll
    for (int i = 0; i < 2; i++) {
        float4 q = p[lane + 32 * i];
        s += q.x * q.x + q.y * q.y + q.z * q.z + q.w * q.w;
    }
#pragma unroll
    for (int off = 16; off; off >>= 1)
        s += __shfl_xor_sync(0xffffffffu, s, off);
    if (lane == 0) {
        if (which == 0) g_xsq[warp] = s;
        else            g_csq[warp] = s;
    }
}

// ---------------------------------------------------------------------------
// Main kernel: each CTA owns TM=64 rows, loops over all K codes in TN=64
// tiles, computes dot products via smem-tiled register-blocked FMA, and
// carries a running (min d2, argmin) per row. Writes argmin (as float) to
// out_idx.
// ---------------------------------------------------------------------------
__global__ __launch_bounds__(256) void vq_argmin(const float* __restrict__ x,
                                                 const float* __restrict__ cb,
                                                 float* __restrict__ out_idx) {
    __shared__ float xs[DCHUNK][TM + 4];   // row stride 68 floats = 272B (16B aligned)
    __shared__ float cs[DCHUNK][TN + 4];

    const int tid = threadIdx.x;
    const int tx = tid & 15;          // 0..15 -> column group
    const int ty = tid >> 4;          // 0..15 -> row group
    const int rowBase = blockIdx.x * TM;

    float best[4];
    int   besti[4];
    float xsq_r[4];
#pragma unroll
    for (int i = 0; i < 4; i++) {
        best[i] = CUDART_INF_F;
        besti[i] = 0;
        xsq_r[i] = g_xsq[rowBase + ty * 4 + i];
    }

    const int lr  = tid >> 2;   // 0..63  tile row for loads
    const int ldq = tid & 3;    // 0..3   float4 index within d-chunk

    for (int kt = 0; kt < KCODES; kt += TN) {
        float acc[4][4];
#pragma unroll
        for (int i = 0; i < 4; i++)
#pragma unroll
            for (int j = 0; j < 4; j++) acc[i][j] = 0.f;

        for (int d0 = 0; d0 < DIM; d0 += DCHUNK) {
            // Cooperative loads: 64 rows x 16 d each, one float4 per thread.
            float4 vx = *(const float4*)&x[(size_t)(rowBase + lr) * DIM + d0 + ldq * 4];
            float4 vc = *(const float4*)&cb[(size_t)(kt + lr) * DIM + d0 + ldq * 4];
            xs[ldq * 4 + 0][lr] = vx.x;
            xs[ldq * 4 + 1][lr] = vx.y;
            xs[ldq * 4 + 2][lr] = vx.z;
            xs[ldq * 4 + 3][lr] = vx.w;
            cs[ldq * 4 + 0][lr] = vc.x;
            cs[ldq * 4 + 1][lr] = vc.y;
            cs[ldq * 4 + 2][lr] = vc.z;
            cs[ldq * 4 + 3][lr] = vc.w;
            __syncthreads();

#pragma unroll
            for (int dd = 0; dd < DCHUNK; dd++) {
                float4 a = *(const float4*)&xs[dd][ty * 4];
                float4 b = *(const float4*)&cs[dd][tx * 4];
                float ar[4] = {a.x, a.y, a.z, a.w};
                float br[4] = {b.x, b.y, b.z, b.w};
#pragma unroll
                for (int i = 0; i < 4; i++)
#pragma unroll
                    for (int j = 0; j < 4; j++)
                        acc[i][j] = fmaf(ar[i], br[j], acc[i][j]);
            }
            __syncthreads();
        }

        // Epilogue for this K tile: d2 = xsq - 2*dot + csq, update running min.
#pragma unroll
        for (int j = 0; j < 4; j++) {
            int k = kt + tx * 4 + j;
            float cq = g_csq[k];
#pragma unroll
            for (int i = 0; i < 4; i++) {
                float d = xsq_r[i] - 2.0f * acc[i][j] + cq;
                if (d < best[i]) { best[i] = d; besti[i] = k; }
            }
        }
    }

    // Reduce the 16 column-group lanes (same ty, tx=0..15 are consecutive
    // lanes within a warp) down to a single (min, argmin) per row.
#pragma unroll
    for (int i = 0; i < 4; i++) {
        float b = best[i];
        int bi = besti[i];
#pragma unroll
        for (int off = 8; off; off >>= 1) {
            float ob = __shfl_down_sync(0xffffffffu, b, off, 16);
            int   oi = __shfl_down_sync(0xffffffffu, bi, off, 16);
            if (ob < b || (ob == b && oi < bi)) { b = ob; bi = oi; }
        }
        if (tx == 0) out_idx[rowBase + ty * 4 + i] = (float)bi;
    }
}

// ---------------------------------------------------------------------------
// Gather: quantized[row] = codebook[idx[row]] (256 floats per row).
// 4 rows per 256-thread block, one float4 per thread.
// ---------------------------------------------------------------------------
__global__ __launch_bounds__(256) void vq_gather(const float* __restrict__ cb,
                                                 const float* __restrict__ idxf,
                                                 float* __restrict__ outq) {
    int row = blockIdx.x * 4 + (threadIdx.x >> 6);
    int t = threadIdx.x & 63;
    int k = (int)idxf[row];
    float4 v = *(const float4*)&cb[(size_t)k * DIM + t * 4];
    *(float4*)&outq[(size_t)row * DIM + t * 4] = v;
}

// ---------------------------------------------------------------------------
extern "C" void kernel_launch(void* const* d_in, const int* in_sizes, int n_in,
                              void* d_out, int out_size) {
    const float* x  = (const float*)d_in[0];   // [8, 4096, 256] f32
    const float* cb = (const float*)d_in[1];   // [8192, 256] f32
    float* out = (float*)d_out;
    float* out_idx = out;               // [32768] indices (as float)
    float* out_q   = out + NROWS;       // [32768, 256] quantized

    // Row norms: one warp per row.
    vq_rownorm<<<(NROWS * 32) / 256, 256>>>(x, NROWS, 0);
    vq_rownorm<<<(KCODES * 32) / 256, 256>>>(cb, KCODES, 1);

    // Argmin over all codes.
    vq_argmin<<<NROWS / TM, 256>>>(x, cb, out_idx);

    // Gather quantized vectors.
    vq_gather<<<NROWS / 4, 256>>>(cb, out_idx, out_q);
}

// round 3
// speedup vs baseline: 3.2690x; 3.2690x over previous
#include <cuda_runtime.h>
#include <cuda_bf16.h>
#include <cstdint>
#include <math_constants.h>

// ---------------------------------------------------------------------------
// Problem constants
// ---------------------------------------------------------------------------
#define NROWS  32768        // 8 * 4096 query rows
#define KCODES 8192
#define DIM    256          // GEMM-K
#define NTILE  128          // codes per N-tile
#define NTILES (KCODES / NTILE)     // 64

// SMEM layout (bytes)
#define ROWA       528      // 256 bf16 + 8 pad  (conflict-free ldmatrix)
#define A_LO_OFF   67584    // 128*528
#define SM_B       135168   // 2*67584
#define MAT_STRIDE 18432    // 128 * 144
#define BUF_STRIDE 36864    // hi+lo
#define ROWB       144      // 64 bf16 + 8 pad
#define SM_CSQ     208896   // 135168 + 2*36864
#define SMEM_TOTAL 209408

// ---------------------------------------------------------------------------
// Device scratch (no allocations allowed)
// ---------------------------------------------------------------------------
__device__ uint4 g_cb_hi4[KCODES * DIM / 8];   // bf16x2 words packed as uint4
__device__ uint4 g_cb_lo4[KCODES * DIM / 8];
__device__ __align__(16) float g_csq[KCODES];
__device__ int   g_cand[NROWS * 2];

// ---------------------------------------------------------------------------
// PTX helpers (base ISA only: ldmatrix / mma.sync / cp.async)
// ---------------------------------------------------------------------------
__device__ __forceinline__ uint32_t smem_to_u32(const void* smem_ptr) {
    uint32_t addr;
    asm("{ .reg .u64 tmp; cvta.to.shared.u64 tmp, %1; cvt.u32.u64 %0, tmp; }"
        : "=r"(addr) : "l"(smem_ptr));
    return addr;
}

#define CP_ASYNC16(dst, src) \
    asm volatile("cp.async.cg.shared.global [%0], [%1], 16;" \
        :: "r"((uint32_t)(dst)), "l"((const void*)(src)) : "memory")
#define CP_COMMIT() asm volatile("cp.async.commit_group;" ::: "memory")
#define CP_WAIT(n)  asm volatile("cp.async.wait_group %0;" :: "n"(n) : "memory")

#define LDSM_X4(r, addr) \
    asm volatile("ldmatrix.sync.aligned.m8n8.x4.shared.b16 {%0,%1,%2,%3}, [%4];" \
        : "=r"((r)[0]), "=r"((r)[1]), "=r"((r)[2]), "=r"((r)[3]) : "r"(addr))
#define LDSM_X2(r, addr) \
    asm volatile("ldmatrix.sync.aligned.m8n8.x2.shared.b16 {%0,%1}, [%2];" \
        : "=r"((r)[0]), "=r"((r)[1]) : "r"(addr))

#define MMA_BF16(c, a, b) \
    asm volatile("mma.sync.aligned.m16n8k16.row.col.f32.bf16.bf16.f32 " \
        "{%0,%1,%2,%3}, {%4,%5,%6,%7}, {%8,%9}, {%0,%1,%2,%3};" \
        : "+f"((c)[0]), "+f"((c)[1]), "+f"((c)[2]), "+f"((c)[3]) \
        : "r"((a)[0]), "r"((a)[1]), "r"((a)[2]), "r"((a)[3]), \
          "r"((b)[0]), "r"((b)[1]))

// ---------------------------------------------------------------------------
// hi/lo bf16 split of a float pair -> two packed bf16x2 words
// ---------------------------------------------------------------------------
__device__ __forceinline__ void split2(float a, float b, uint32_t& h, uint32_t& l) {
    __nv_bfloat16 ha = __float2bfloat16_rn(a);
    __nv_bfloat16 hb = __float2bfloat16_rn(b);
    __nv_bfloat16 la = __float2bfloat16_rn(a - __bfloat162float(ha));
    __nv_bfloat16 lb = __float2bfloat16_rn(b - __bfloat162float(hb));
    __nv_bfloat162 hp; hp.x = ha; hp.y = hb;
    __nv_bfloat162 lp; lp.x = la; lp.y = lb;
    h = *reinterpret_cast<uint32_t*>(&hp);
    l = *reinterpret_cast<uint32_t*>(&lp);
}

// ---------------------------------------------------------------------------
// Codebook prep: one warp per code row. bf16 hi/lo (k-linear packed) + csq.
// ---------------------------------------------------------------------------
__global__ __launch_bounds__(256) void vq_prep(const float* __restrict__ cb) {
    int row  = blockIdx.x * 8 + (threadIdx.x >> 5);
    int lane = threadIdx.x & 31;
    const float4* cr = (const float4*)(cb + (size_t)row * DIM);
    float sq = 0.f;
    uint32_t hw[4], lw[4];
#pragma unroll
    for (int q = 0; q < 2; q++) {
        float4 v = cr[lane * 2 + q];
        sq += v.x * v.x + v.y * v.y + v.z * v.z + v.w * v.w;
        split2(v.x, v.y, hw[q * 2 + 0], lw[q * 2 + 0]);
        split2(v.z, v.w, hw[q * 2 + 1], lw[q * 2 + 1]);
    }
    g_cb_hi4[row * 32 + lane] = make_uint4(hw[0], hw[1], hw[2], hw[3]);
    g_cb_lo4[row * 32 + lane] = make_uint4(lw[0], lw[1], lw[2], lw[3]);
#pragma unroll
    for (int off = 16; off; off >>= 1) sq += __shfl_xor_sync(0xffffffffu, sq, off);
    if (lane == 0) g_csq[row] = sq;
}

// ---------------------------------------------------------------------------
// B stage loader: 128 codes x 64 bf16 (hi and lo) into padded smem rows.
// ---------------------------------------------------------------------------
__device__ __forceinline__ void load_b_stage(uint32_t sbase, int buf, int ktile,
                                             int s, int tid) {
    const char* hi_src = (const char*)g_cb_hi4 + (size_t)ktile * NTILE * 512 + s * 128;
    const char* lo_src = (const char*)g_cb_lo4 + (size_t)ktile * NTILE * 512 + s * 128;
    uint32_t bhi = sbase + SM_B + buf * BUF_STRIDE;
    uint32_t blo = bhi + MAT_STRIDE;
#pragma unroll
    for (int u = tid; u < 1024; u += 256) {
        int n = u >> 3, j = u & 7;
        CP_ASYNC16(bhi + n * ROWB + j * 16, hi_src + (size_t)n * 512 + j * 16);
        CP_ASYNC16(blo + n * ROWB + j * 16, lo_src + (size_t)n * 512 + j * 16);
    }
}

// merge (C1,J1,C2,J2) into running top-2 (B1,I1,B2,I2)
#define MERGE2(B1, I1, B2, I2, C1, J1, C2, J2) do { \
    if ((C1) < (B1)) { \
        float _nb2; int _ni2; \
        if ((B1) < (C2)) { _nb2 = (B1); _ni2 = (I1); } \
        else             { _nb2 = (C2); _ni2 = (J2); } \
        (B1) = (C1); (I1) = (J1); (B2) = _nb2; (I2) = _ni2; \
    } else if ((C1) < (B2)) { (B2) = (C1); (I2) = (J1); } \
} while (0)

// ---------------------------------------------------------------------------
// Main kernel: 128 rows/CTA, all 8192 codes, bf16 hi/lo 3-pass mma.sync,
// running global top-2 per row -> g_cand.
// ---------------------------------------------------------------------------
__global__ __launch_bounds__(256, 1) void vq_main(const float* __restrict__ x) {
    extern __shared__ char smem[];
    const uint32_t sbase = smem_to_u32(smem);
    const int tid  = threadIdx.x;
    const int wid  = tid >> 5;
    const int lane = tid & 31;
    const int warp_m = wid >> 2;            // 0..1  (64-row band)
    const int warp_n = wid & 3;             // 0..3  (32-col band)
    const int rowBase = blockIdx.x * 128;

    // ---- Prologue: split x rows into smem A_hi / A_lo (row stride 528B) ----
    {
        int r = tid >> 1, h = tid & 1;
        const float4* xr = (const float4*)(x + (size_t)(rowBase + r) * DIM + h * 128);
        uint32_t* ah = (uint32_t*)(smem + r * ROWA + h * 256);
        uint32_t* al = (uint32_t*)(smem + A_LO_OFF + r * ROWA + h * 256);
#pragma unroll
        for (int q = 0; q < 32; q++) {
            float4 v = xr[q];
            uint32_t h0, l0, h1, l1;
            split2(v.x, v.y, h0, l0);
            split2(v.z, v.w, h1, l1);
            ah[q * 2 + 0] = h0; ah[q * 2 + 1] = h1;
            al[q * 2 + 0] = l0; al[q * 2 + 1] = l1;
        }
    }

    // per-lane ldmatrix base addresses
    const uint32_t aBase = sbase + (uint32_t)((warp_m * 64 + (lane & 15)) * ROWA
                                              + ((lane >> 4) & 1) * 16);
    const uint32_t bLane = (uint32_t)((warp_n * 32 + (lane & 7)) * ROWB
                                      + ((lane >> 3) & 1) * 16);

    float b1r[8], b2r[8];
    int   i1r[8], i2r[8];
#pragma unroll
    for (int s = 0; s < 8; s++) {
        b1r[s] = CUDART_INF_F; b2r[s] = CUDART_INF_F; i1r[s] = 0; i2r[s] = 1;
    }

    for (int ktile = 0; ktile < NTILES; ktile++) {
        __syncthreads();    // A ready (first iter) / prev epilogue done with csq+B
        load_b_stage(sbase, 0, ktile, 0, tid);
        if (tid < 32) {
            CP_ASYNC16(sbase + SM_CSQ + tid * 16,
                       (const char*)g_csq + (size_t)ktile * 512 + tid * 16);
        }
        CP_COMMIT();

        float c[4][4][4];
#pragma unroll
        for (int a = 0; a < 4; a++)
#pragma unroll
            for (int b = 0; b < 4; b++)
#pragma unroll
                for (int v = 0; v < 4; v++) c[a][b][v] = 0.f;

        for (int s = 0; s < 4; s++) {
            if (s < 3) {
                load_b_stage(sbase, (s + 1) & 1, ktile, s + 1, tid);
                CP_COMMIT();
                CP_WAIT(1);
            } else {
                CP_WAIT(0);
            }
            __syncthreads();
            const uint32_t bufB = sbase + SM_B + ((s & 1) ? BUF_STRIDE : 0);
#pragma unroll
            for (int kk = 0; kk < 4; kk++) {
                const int kg = s * 64 + kk * 16;
                uint32_t ah[4][4], al[4][4], bh[4][2], bl[4][2];
#pragma unroll
                for (int mt = 0; mt < 4; mt++) {
                    uint32_t aa = aBase + mt * (16 * ROWA) + kg * 2;
                    LDSM_X4(ah[mt], aa);
                    LDSM_X4(al[mt], aa + A_LO_OFF);
                }
#pragma unroll
                for (int nt = 0; nt < 4; nt++) {
                    uint32_t ba = bufB + bLane + nt * (8 * ROWB) + kk * 32;
                    LDSM_X2(bh[nt], ba);
                    LDSM_X2(bl[nt], ba + MAT_STRIDE);
                }
#pragma unroll
                for (int mt = 0; mt < 4; mt++)
#pragma unroll
                    for (int nt = 0; nt < 4; nt++) {
                        MMA_BF16(c[mt][nt], ah[mt], bh[nt]);
                        MMA_BF16(c[mt][nt], ah[mt], bl[nt]);
                        MMA_BF16(c[mt][nt], al[mt], bh[nt]);
                    }
            }
            __syncthreads();   // compute done before next stage overwrites buf
        }

        // ---- epilogue: scores + running top-2 ----
        const float* csq_s = (const float*)(smem + SM_CSQ);
#pragma unroll
        for (int mt = 0; mt < 4; mt++)
#pragma unroll
            for (int nt = 0; nt < 4; nt++)
#pragma unroll
                for (int v = 0; v < 4; v++) {
                    int ncol = warp_n * 32 + nt * 8 + 2 * (lane & 3) + (v & 1);
                    float sc = fmaf(-2.0f, c[mt][nt][v], csq_s[ncol]);
                    int k = ktile * NTILE + ncol;
                    int slot = mt * 2 + (v >> 1);
                    if (sc < b1r[slot]) {
                        b2r[slot] = b1r[slot]; i2r[slot] = i1r[slot];
                        b1r[slot] = sc;        i1r[slot] = k;
                    } else if (sc < b2r[slot]) {
                        b2r[slot] = sc; i2r[slot] = k;
                    }
                }
    }

    // ---- lane-quad merge (lanes sharing a row differ in lane&3) ----
#pragma unroll
    for (int slot = 0; slot < 8; slot++) {
        float B1 = b1r[slot], B2 = b2r[slot];
        int   I1 = i1r[slot], I2 = i2r[slot];
#pragma unroll
        for (int off = 1; off <= 2; off <<= 1) {
            float C1 = __shfl_xor_sync(0xffffffffu, B1, off);
            int   J1 = __shfl_xor_sync(0xffffffffu, I1, off);
            float C2 = __shfl_xor_sync(0xffffffffu, B2, off);
            int   J2 = __shfl_xor_sync(0xffffffffu, I2, off);
            MERGE2(B1, I1, B2, I2, C1, J1, C2, J2);
        }
        b1r[slot] = B1; i1r[slot] = I1; b2r[slot] = B2; i2r[slot] = I2;
    }

    __syncthreads();
    float* mb1 = (float*)(smem + SM_B);
    int*   mi1 = (int*)  (smem + SM_B + 2048);
    float* mb2 = (float*)(smem + SM_B + 4096);
    int*   mi2 = (int*)  (smem + SM_B + 6144);
    if ((lane & 3) == 0) {
#pragma unroll
        for (int slot = 0; slot < 8; slot++) {
            int row = warp_m * 64 + (slot >> 1) * 16 + (slot & 1) * 8 + (lane >> 2);
            int idx = warp_n * 128 + row;
            mb1[idx] = b1r[slot]; mi1[idx] = i1r[slot];
            mb2[idx] = b2r[slot]; mi2[idx] = i2r[slot];
        }
    }
    __syncthreads();
    if (tid < 128) {
        float B1 = mb1[tid], B2 = mb2[tid];
        int   I1 = mi1[tid], I2 = mi2[tid];
#pragma unroll
        for (int w = 1; w < 4; w++) {
            float C1 = mb1[w * 128 + tid]; int J1 = mi1[w * 128 + tid];
            float C2 = mb2[w * 128 + tid]; int J2 = mi2[w * 128 + tid];
            MERGE2(B1, I1, B2, I2, C1, J1, C2, J2);
        }
        g_cand[(rowBase + tid) * 2 + 0] = I1;
        g_cand[(rowBase + tid) * 2 + 1] = I2;
    }
}

// ---------------------------------------------------------------------------
// Exact fp32 rescore of the two candidates + gather. One warp per row.
// ---------------------------------------------------------------------------
__global__ __launch_bounds__(256) void vq_rescore(const float* __restrict__ x,
                                                  const float* __restrict__ cb,
                                                  float* __restrict__ out) {
    int row  = blockIdx.x * 8 + (threadIdx.x >> 5);
    int lane = threadIdx.x & 31;
    int k0 = g_cand[row * 2 + 0];
    int k1 = g_cand[row * 2 + 1];
    const float4* xr = (const float4*)(x  + (size_t)row * DIM);
    const float4* c0 = (const float4*)(cb + (size_t)k0 * DIM);
    const float4* c1 = (const float4*)(cb + (size_t)k1 * DIM);
    float d0 = 0.f, d1 = 0.f;
#pragma unroll
    for (int i = 0; i < 2; i++) {
        float4 xv = xr[lane + 32 * i];
        float4 a  = c0[lane + 32 * i];
        float4 b  = c1[lane + 32 * i];
        d0 += xv.x * a.x + xv.y * a.y + xv.z * a.z + xv.w * a.w;
        d1 += xv.x * b.x + xv.y * b.y + xv.z * b.z + xv.w * b.w;
    }
#pragma unroll
    for (int off = 16; off; off >>= 1) {
        d0 += __shfl_xor_sync(0xffffffffu, d0, off);
        d1 += __shfl_xor_sync(0xffffffffu, d1, off);
    }
    float s0 = fmaf(-2.f, d0, g_csq[k0]);
    float s1 = fmaf(-2.f, d1, g_csq[k1]);
    int w = k0;
    if (s1 < s0 || (s1 == s0 && k1 < k0)) w = k1;
    if (lane == 0) out[row] = (float)w;
    const float4* cw = (const float4*)(cb + (size_t)w * DIM);
    float4* oq = (float4*)(out + NROWS + (size_t)row * DIM);
#pragma unroll
    for (int i = 0; i < 2; i++) oq[lane + 32 * i] = cw[lane + 32 * i];
}

// ---------------------------------------------------------------------------
extern "C" void kernel_launch(void* const* d_in, const int* in_sizes, int n_in,
                              void* d_out, int out_size) {
    const float* x  = (const float*)d_in[0];   // [8, 4096, 256] f32
    const float* cb = (const float*)d_in[1];   // [8192, 256] f32
    float* out = (float*)d_out;

    cudaFuncSetAttribute(vq_main, cudaFuncAttributeMaxDynamicSharedMemorySize,
                         SMEM_TOTAL);

    vq_prep<<<KCODES / 8, 256>>>(cb);
    vq_main<<<NROWS / 128, 256, SMEM_TOTAL>>>(x);
    vq_rescore<<<NROWS / 8, 256>>>(x, cb, out);
}

// round 4
// speedup vs baseline: 3.7344x; 1.1423x over previous
#include <cuda_runtime.h>
#include <cuda_bf16.h>
#include <cstdint>
#include <math_constants.h>

// ---------------------------------------------------------------------------
// Problem constants
// ---------------------------------------------------------------------------
#define NROWS  32768        // 8 * 4096 query rows
#define KCODES 8192
#define DIM    256          // GEMM-K
#define MT     128          // rows per CTA
#define NTILE  256          // codes per N-tile
#define KTILES (KCODES / NTILE)       // 32
#define NSTG   (KTILES * 16)          // 512 k16-stages total

// SMEM layout (bytes)
#define ROWA        528     // 256 bf16 + 8 pad (conflict-free ldmatrix)
#define A_LO_OFF    67584   // 128*528
#define SM_B        135168  // ring of 4 stages
#define STAGE_BYTES 12288   // 256 codes * 48B
#define ROWB        48      // 32B k-slice + 16 pad
#define SM_CSQ      184320  // 2 x 1KB double-buffered csq
#define SMEM_TOTAL  186368

// ---------------------------------------------------------------------------
// Device scratch (no allocations allowed)
// ---------------------------------------------------------------------------
__device__ uint4 g_cb_hi4[KCODES * DIM / 8];   // bf16 hi, 512B per code row
__device__ __align__(16) float g_csq[KCODES];
__device__ int   g_cand[NROWS * 4];

// ---------------------------------------------------------------------------
// PTX helpers (base ISA only: ldmatrix / mma.sync / cp.async)
// ---------------------------------------------------------------------------
__device__ __forceinline__ uint32_t smem_to_u32(const void* smem_ptr) {
    uint32_t addr;
    asm("{ .reg .u64 tmp; cvta.to.shared.u64 tmp, %1; cvt.u32.u64 %0, tmp; }"
        : "=r"(addr) : "l"(smem_ptr));
    return addr;
}

#define CP_ASYNC16(dst, src) \
    asm volatile("cp.async.cg.shared.global [%0], [%1], 16;" \
        :: "r"((uint32_t)(dst)), "l"((const void*)(src)) : "memory")
#define CP_COMMIT() asm volatile("cp.async.commit_group;" ::: "memory")
#define CP_WAIT(n)  asm volatile("cp.async.wait_group %0;" :: "n"(n) : "memory")

#define LDSM_X4(r, addr) \
    asm volatile("ldmatrix.sync.aligned.m8n8.x4.shared.b16 {%0,%1,%2,%3}, [%4];" \
        : "=r"((r)[0]), "=r"((r)[1]), "=r"((r)[2]), "=r"((r)[3]) : "r"(addr))

#define MMA_BF16(c, a, b) \
    asm volatile("mma.sync.aligned.m16n8k16.row.col.f32.bf16.bf16.f32 " \
        "{%0,%1,%2,%3}, {%4,%5,%6,%7}, {%8,%9}, {%0,%1,%2,%3};" \
        : "+f"((c)[0]), "+f"((c)[1]), "+f"((c)[2]), "+f"((c)[3]) \
        : "r"((a)[0]), "r"((a)[1]), "r"((a)[2]), "r"((a)[3]), \
          "r"((b)[0]), "r"((b)[1]))

// merge candidate (C1,J1) then (C2,J2) into running top-2 (B1,I1,B2,I2)
#define MERGE2(B1, I1, B2, I2, C1, J1, C2, J2) do { \
    if ((C1) < (B1)) { \
        float _nb2; int _ni2; \
        if ((B1) < (C2)) { _nb2 = (B1); _ni2 = (I1); } \
        else             { _nb2 = (C2); _ni2 = (J2); } \
        (B1) = (C1); (I1) = (J1); (B2) = _nb2; (I2) = _ni2; \
    } else if ((C1) < (B2)) { (B2) = (C1); (I2) = (J1); } \
} while (0)

// ---------------------------------------------------------------------------
// hi/lo bf16 split of a float pair -> two packed bf16x2 words
// ---------------------------------------------------------------------------
__device__ __forceinline__ void split2(float a, float b, uint32_t& h, uint32_t& l) {
    __nv_bfloat16 ha = __float2bfloat16_rn(a);
    __nv_bfloat16 hb = __float2bfloat16_rn(b);
    __nv_bfloat16 la = __float2bfloat16_rn(a - __bfloat162float(ha));
    __nv_bfloat16 lb = __float2bfloat16_rn(b - __bfloat162float(hb));
    __nv_bfloat162 hp; hp.x = ha; hp.y = hb;
    __nv_bfloat162 lp; lp.x = la; lp.y = lb;
    h = *reinterpret_cast<uint32_t*>(&hp);
    l = *reinterpret_cast<uint32_t*>(&lp);
}

// ---------------------------------------------------------------------------
// Codebook prep: one warp per code row. bf16 hi only + fp32 csq.
// ---------------------------------------------------------------------------
__global__ __launch_bounds__(256) void vq_prep(const float* __restrict__ cb) {
    int row  = blockIdx.x * 8 + (threadIdx.x >> 5);
    int lane = threadIdx.x & 31;
    const float4* cr = (const float4*)(cb + (size_t)row * DIM);
    float sq = 0.f;
    uint32_t hw[4];
#pragma unroll
    for (int q = 0; q < 2; q++) {
        float4 v = cr[lane * 2 + q];
        sq += v.x * v.x + v.y * v.y + v.z * v.z + v.w * v.w;
        __nv_bfloat162 p0; p0.x = __float2bfloat16_rn(v.x); p0.y = __float2bfloat16_rn(v.y);
        __nv_bfloat162 p1; p1.x = __float2bfloat16_rn(v.z); p1.y = __float2bfloat16_rn(v.w);
        hw[q * 2 + 0] = *reinterpret_cast<uint32_t*>(&p0);
        hw[q * 2 + 1] = *reinterpret_cast<uint32_t*>(&p1);
    }
    g_cb_hi4[row * 32 + lane] = make_uint4(hw[0], hw[1], hw[2], hw[3]);
#pragma unroll
    for (int off = 16; off; off >>= 1) sq += __shfl_xor_sync(0xffffffffu, sq, off);
    if (lane == 0) g_csq[row] = sq;
}

// ---------------------------------------------------------------------------
// Prefetch one k16 stage (256 codes x 32B) into the ring.
// ---------------------------------------------------------------------------
__device__ __forceinline__ void prefetch_stage(uint32_t sbase, int gs, int tid) {
    int ktile = gs >> 4, s = gs & 15;
    const char* src = (const char*)g_cb_hi4 + ((size_t)ktile * NTILE + tid) * 512 + s * 32;
    uint32_t dst = sbase + SM_B + (uint32_t)(gs & 3) * STAGE_BYTES + tid * ROWB;
    CP_ASYNC16(dst, src);
    CP_ASYNC16(dst + 16, src + 16);
}

// ---------------------------------------------------------------------------
// Main kernel: 128 rows/CTA, 2-pass bf16 (A hi+lo, B hi), 64x64 warp tiles,
// 4-deep cp.async ring, per-row top-2 w/ skip-test epilogue -> top-4 cands.
// ---------------------------------------------------------------------------
__global__ __launch_bounds__(256, 1) void vq_main(const float* __restrict__ x) {
    extern __shared__ char smem[];
    const uint32_t sbase = smem_to_u32(smem);
    const int tid  = threadIdx.x;
    const int wid  = tid >> 5;
    const int lane = tid & 31;
    const int wm = wid >> 2;                // 0..1 : 64-row band
    const int wn = wid & 3;                 // 0..3 : 64-col band
    const int rowBase = blockIdx.x * MT;

    // ---- A split into smem hi/lo (row stride 528B) ----
    {
        int r = tid >> 1, h = tid & 1;
        const float4* xr = (const float4*)(x + (size_t)(rowBase + r) * DIM + h * 128);
        uint32_t* ah = (uint32_t*)(smem + r * ROWA + h * 256);
        uint32_t* al = (uint32_t*)(smem + A_LO_OFF + r * ROWA + h * 256);
#pragma unroll
        for (int q = 0; q < 32; q++) {
            float4 v = xr[q];
            uint32_t h0, l0, h1, l1;
            split2(v.x, v.y, h0, l0);
            split2(v.z, v.w, h1, l1);
            ah[q * 2 + 0] = h0; ah[q * 2 + 1] = h1;
            al[q * 2 + 0] = l0; al[q * 2 + 1] = l1;
        }
    }

    // ---- prologue prefetch: stages 0..2 + csq tile 0 ----
    prefetch_stage(sbase, 0, tid);
    if (tid < 64) CP_ASYNC16(sbase + SM_CSQ + tid * 16, (const char*)g_csq + tid * 16);
    CP_COMMIT();
    prefetch_stage(sbase, 1, tid); CP_COMMIT();
    prefetch_stage(sbase, 2, tid); CP_COMMIT();

    // per-lane ldmatrix base addresses
    const uint32_t aHiB = sbase + (uint32_t)((wm * 64 + (lane & 15)) * ROWA
                                             + ((lane >> 4) & 1) * 16);
    const uint32_t aLoB = aHiB + A_LO_OFF;
    const uint32_t bOff = (uint32_t)((wn * 64 + ((lane >> 4) & 1) * 8 + (lane & 7)) * ROWB
                                     + ((lane >> 3) & 1) * 16);

    float c[4][8][4];
#pragma unroll
    for (int a = 0; a < 4; a++)
#pragma unroll
        for (int b = 0; b < 8; b++)
#pragma unroll
            for (int v = 0; v < 4; v++) c[a][b][v] = 0.f;

    float b1r[8], b2r[8];
    int   i1r[8], i2r[8];
#pragma unroll
    for (int s = 0; s < 8; s++) {
        b1r[s] = CUDART_INF_F; b2r[s] = CUDART_INF_F; i1r[s] = 0; i2r[s] = 1;
    }

    for (int gs = 0; gs < NSTG; gs++) {
        CP_WAIT(2);
        __syncthreads();
        if (gs + 3 < NSTG) {
            prefetch_stage(sbase, gs + 3, tid);
            if ((((gs + 3) & 15) == 0) && tid < 64) {
                int nk = (gs + 3) >> 4;
                CP_ASYNC16(sbase + SM_CSQ + (nk & 1) * 1024 + tid * 16,
                           (const char*)g_csq + (size_t)nk * 1024 + tid * 16);
            }
        }
        CP_COMMIT();

        const int s = gs & 15;
        const uint32_t sb = sbase + SM_B + (uint32_t)(gs & 3) * STAGE_BYTES;

        uint32_t bf[4][4];
#pragma unroll
        for (int np = 0; np < 4; np++) LDSM_X4(bf[np], sb + bOff + np * (16 * ROWB));
        uint32_t ah[4][4];
#pragma unroll
        for (int mt = 0; mt < 4; mt++) LDSM_X4(ah[mt], aHiB + mt * (16 * ROWA) + s * 32);
#pragma unroll
        for (int mt = 0; mt < 4; mt++)
#pragma unroll
            for (int np = 0; np < 4; np++) {
                MMA_BF16(c[mt][2 * np + 0], ah[mt], bf[np]);
                MMA_BF16(c[mt][2 * np + 1], ah[mt], bf[np] + 2);
            }
        uint32_t al[4][4];
#pragma unroll
        for (int mt = 0; mt < 4; mt++) LDSM_X4(al[mt], aLoB + mt * (16 * ROWA) + s * 32);
#pragma unroll
        for (int mt = 0; mt < 4; mt++)
#pragma unroll
            for (int np = 0; np < 4; np++) {
                MMA_BF16(c[mt][2 * np + 0], al[mt], bf[np]);
                MMA_BF16(c[mt][2 * np + 1], al[mt], bf[np] + 2);
            }

        if (s == 15) {
            const int ktile = gs >> 4;
            const float* csq_s = (const float*)(smem + SM_CSQ + (ktile & 1) * 1024) + wn * 64;
            float csqr[16];
#pragma unroll
            for (int nt = 0; nt < 8; nt++) {
                csqr[nt * 2 + 0] = csq_s[nt * 8 + (lane & 3) * 2 + 0];
                csqr[nt * 2 + 1] = csq_s[nt * 8 + (lane & 3) * 2 + 1];
            }
            const int kb = ktile * NTILE + wn * 64 + (lane & 3) * 2;
#pragma unroll
            for (int slot = 0; slot < 8; slot++) {
                const int mt = slot >> 1, h = slot & 1;
                float m = CUDART_INF_F;
#pragma unroll
                for (int nt = 0; nt < 8; nt++) {
                    m = fminf(m, fmaf(-2.f, c[mt][nt][h * 2 + 0], csqr[nt * 2 + 0]));
                    m = fminf(m, fmaf(-2.f, c[mt][nt][h * 2 + 1], csqr[nt * 2 + 1]));
                }
                if (m < b2r[slot]) {
#pragma unroll
                    for (int nt = 0; nt < 8; nt++)
#pragma unroll
                        for (int u = 0; u < 2; u++) {
                            float sc = fmaf(-2.f, c[mt][nt][h * 2 + u], csqr[nt * 2 + u]);
                            int k = kb + nt * 8 + u;
                            if (sc < b1r[slot]) {
                                b2r[slot] = b1r[slot]; i2r[slot] = i1r[slot];
                                b1r[slot] = sc;        i1r[slot] = k;
                            } else if (sc < b2r[slot]) {
                                b2r[slot] = sc; i2r[slot] = k;
                            }
                        }
                }
            }
#pragma unroll
            for (int a = 0; a < 4; a++)
#pragma unroll
                for (int b = 0; b < 8; b++)
#pragma unroll
                    for (int v = 0; v < 4; v++) c[a][b][v] = 0.f;
        }
    }

    // ---- lane-quad merge (lanes sharing a row differ in lane&3) ----
#pragma unroll
    for (int slot = 0; slot < 8; slot++) {
        float B1 = b1r[slot], B2 = b2r[slot];
        int   I1 = i1r[slot], I2 = i2r[slot];
#pragma unroll
        for (int off = 1; off <= 2; off <<= 1) {
            float C1 = __shfl_xor_sync(0xffffffffu, B1, off);
            int   J1 = __shfl_xor_sync(0xffffffffu, I1, off);
            float C2 = __shfl_xor_sync(0xffffffffu, B2, off);
            int   J2 = __shfl_xor_sync(0xffffffffu, I2, off);
            MERGE2(B1, I1, B2, I2, C1, J1, C2, J2);
        }
        b1r[slot] = B1; i1r[slot] = I1; b2r[slot] = B2; i2r[slot] = I2;
    }

    __syncthreads();
    float* mb1 = (float*)(smem + SM_B);
    int*   mi1 = (int*)  (smem + SM_B + 2048);
    float* mb2 = (float*)(smem + SM_B + 4096);
    int*   mi2 = (int*)  (smem + SM_B + 6144);
    if ((lane & 3) == 0) {
#pragma unroll
        for (int slot = 0; slot < 8; slot++) {
            int row = wm * 64 + (slot >> 1) * 16 + (slot & 1) * 8 + (lane >> 2);
            int idx = wn * 128 + row;
            mb1[idx] = b1r[slot]; mi1[idx] = i1r[slot];
            mb2[idx] = b2r[slot]; mi2[idx] = i2r[slot];
        }
    }
    __syncthreads();
    if (tid < 128) {
        float v[8]; int id[8];
#pragma unroll
        for (int w = 0; w < 4; w++) {
            v[w * 2 + 0] = mb1[w * 128 + tid]; id[w * 2 + 0] = mi1[w * 128 + tid];
            v[w * 2 + 1] = mb2[w * 128 + tid]; id[w * 2 + 1] = mi2[w * 128 + tid];
        }
#pragma unroll
        for (int csel = 0; csel < 4; csel++) {
            float bv = v[0]; int bj = 0;
#pragma unroll
            for (int j = 1; j < 8; j++)
                if (v[j] < bv) { bv = v[j]; bj = j; }
            g_cand[(rowBase + tid) * 4 + csel] = id[bj];
            v[bj] = CUDART_INF_F;
        }
    }
}

// ---------------------------------------------------------------------------
// Exact fp32 rescore of 4 candidates + gather. One warp per row.
// ---------------------------------------------------------------------------
__global__ __launch_bounds__(256) void vq_rescore(const float* __restrict__ x,
                                                  const float* __restrict__ cb,
                                                  float* __restrict__ out) {
    int row  = blockIdx.x * 8 + (threadIdx.x >> 5);
    int lane = threadIdx.x & 31;
    int kc[4];
#pragma unroll
    for (int c = 0; c < 4; c++) kc[c] = g_cand[row * 4 + c];
    const float4* xr = (const float4*)(x + (size_t)row * DIM);
    float4 xv0 = xr[lane], xv1 = xr[lane + 32];
    float d[4];
#pragma unroll
    for (int c = 0; c < 4; c++) {
        const float4* cc = (const float4*)(cb + (size_t)kc[c] * DIM);
        float4 a = cc[lane], b = cc[lane + 32];
        d[c] = xv0.x * a.x + xv0.y * a.y + xv0.z * a.z + xv0.w * a.w
             + xv1.x * b.x + xv1.y * b.y + xv1.z * b.z + xv1.w * b.w;
    }
#pragma unroll
    for (int off = 16; off; off >>= 1)
#pragma unroll
        for (int c = 0; c < 4; c++) d[c] += __shfl_xor_sync(0xffffffffu, d[c], off);
    float best = CUDART_INF_F; int bi = 0x7fffffff;
#pragma unroll
    for (int c = 0; c < 4; c++) {
        float s = fmaf(-2.f, d[c], g_csq[kc[c]]);
        if (s < best || (s == best && kc[c] < bi)) { best = s; bi = kc[c]; }
    }
    if (lane == 0) out[row] = (float)bi;
    const float4* cw = (const float4*)(cb + (size_t)bi * DIM);
    float4* oq = (float4*)(out + NROWS + (size_t)row * DIM);
    oq[lane] = cw[lane];
    oq[lane + 32] = cw[lane + 32];
}

// ---------------------------------------------------------------------------
extern "C" void kernel_launch(void* const* d_in, const int* in_sizes, int n_in,
                              void* d_out, int out_size) {
    const float* x  = (const float*)d_in[0];   // [8, 4096, 256] f32
    const float* cb = (const float*)d_in[1];   // [8192, 256] f32
    float* out = (float*)d_out;

    cudaFuncSetAttribute(vq_main, cudaFuncAttributeMaxDynamicSharedMemorySize,
                         SMEM_TOTAL);

    vq_prep<<<KCODES / 8, 256>>>(cb);
    vq_main<<<NROWS / MT, 256, SMEM_TOTAL>>>(x);
    vq_rescore<<<NROWS / 8, 256>>>(x, cb, out);
}